// round 3
// baseline (speedup 1.0000x reference)
#include <cuda_runtime.h>
#include <math.h>

#define B_ 4
#define LQ 2048
#define LK 2048
#define DM 512
#define NH 2
#define DH 64
#define HD 128   /* NH*DH */

// ---- scratch (static device globals; no allocation) ----
__device__ float g_q[(size_t)B_ * LQ * HD];
__device__ float g_k[(size_t)B_ * LK * HD];
__device__ float g_v[(size_t)B_ * LK * HD];
__device__ float g_ho[(size_t)B_ * LQ * HD];

// =====================================================================
// Generic NN GEMM: C = A(MxK, lda) @ B(KxN, ldb) (+bias), 64x64 tile,
// 256 threads, 4x4 per-thread micro-tile. Batched via blockIdx.z with
// (hi,lo) offsets:  ptr += (z>>1)*offHi + (z&1)*offLo.
// =====================================================================
__global__ __launch_bounds__(256) void gemm_nn(
    const float* __restrict__ A, int lda, long offAhi, long offAlo,
    const float* __restrict__ Bm, int ldb, long offBhi, long offBlo,
    const float* __restrict__ bias,
    float* __restrict__ C, int ldc, long offChi, long offClo,
    int K)
{
    int z = blockIdx.z;
    A  += (long)(z >> 1) * offAhi + (long)(z & 1) * offAlo;
    Bm += (long)(z >> 1) * offBhi + (long)(z & 1) * offBlo;
    C  += (long)(z >> 1) * offChi + (long)(z & 1) * offClo;

    __shared__ float As[64][25];   // [m][kk], stride 25 => conflict-light scalar reads
    __shared__ float Bs[16][80];   // [kk][n], stride 80 floats (320B) => aligned float4

    int tid = threadIdx.x;
    int tx = tid & 15, ty = tid >> 4;
    int row0 = blockIdx.y * 64, col0 = blockIdx.x * 64;

    int lm  = tid >> 2, lk4 = (tid & 3) << 2;   // As loader: 64 rows x 4-float chunk
    int bkk = tid >> 4, bn4 = (tid & 15) << 2;  // Bs loader: 16 k x 4-float chunk

    float acc[4][4] = {};

    for (int k0 = 0; k0 < K; k0 += 16) {
        float4 av = *reinterpret_cast<const float4*>(&A[(size_t)(row0 + lm) * lda + k0 + lk4]);
        float4 bv = *reinterpret_cast<const float4*>(&Bm[(size_t)(k0 + bkk) * ldb + col0 + bn4]);
        As[lm][lk4 + 0] = av.x;
        As[lm][lk4 + 1] = av.y;
        As[lm][lk4 + 2] = av.z;
        As[lm][lk4 + 3] = av.w;
        *reinterpret_cast<float4*>(&Bs[bkk][bn4]) = bv;
        __syncthreads();
        #pragma unroll
        for (int kk = 0; kk < 16; ++kk) {
            float a0 = As[ty * 4 + 0][kk];
            float a1 = As[ty * 4 + 1][kk];
            float a2 = As[ty * 4 + 2][kk];
            float a3 = As[ty * 4 + 3][kk];
            float4 b4 = *reinterpret_cast<const float4*>(&Bs[kk][tx * 4]);
            acc[0][0] += a0 * b4.x; acc[0][1] += a0 * b4.y; acc[0][2] += a0 * b4.z; acc[0][3] += a0 * b4.w;
            acc[1][0] += a1 * b4.x; acc[1][1] += a1 * b4.y; acc[1][2] += a1 * b4.z; acc[1][3] += a1 * b4.w;
            acc[2][0] += a2 * b4.x; acc[2][1] += a2 * b4.y; acc[2][2] += a2 * b4.z; acc[2][3] += a2 * b4.w;
            acc[3][0] += a3 * b4.x; acc[3][1] += a3 * b4.y; acc[3][2] += a3 * b4.z; acc[3][3] += a3 * b4.w;
        }
        __syncthreads();
    }

    #pragma unroll
    for (int i = 0; i < 4; ++i) {
        int r = row0 + ty * 4 + i;
        #pragma unroll
        for (int j = 0; j < 4; ++j) {
            int c = col0 + tx * 4 + j;
            float v = acc[i][j];
            if (bias) v += bias[c];
            C[(size_t)r * ldc + c] = v;
        }
    }
}

// =====================================================================
// Scores: S[b,h,q,k] = tanh( (q . k)/8 ) * 10 ;  masked cols -> -10
// A = q rows (2048 x 64, ld HD), B = k rows (2048 x 64, ld HD), NT product.
// =====================================================================
__global__ __launch_bounds__(256) void gemm_nt_scores(
    const float* __restrict__ qp, const float* __restrict__ kp,
    const int* __restrict__ mask, float* __restrict__ S)
{
    int z = blockIdx.z, b = z >> 1, h = z & 1;
    const float* A  = qp + (size_t)b * LQ * HD + h * DH;
    const float* Bm = kp + (size_t)b * LK * HD + h * DH;
    float* Sout = S + (size_t)z * LQ * LK;

    __shared__ float As[64][25];
    __shared__ float Bs[64][25];

    int tid = threadIdx.x, tx = tid & 15, ty = tid >> 4;
    int row0 = blockIdx.y * 64, col0 = blockIdx.x * 64;
    int lm = tid >> 2, lk4 = (tid & 3) << 2;

    float acc[4][4] = {};

    #pragma unroll
    for (int k0 = 0; k0 < DH; k0 += 16) {
        float4 av = *reinterpret_cast<const float4*>(&A[(size_t)(row0 + lm) * HD + k0 + lk4]);
        float4 bv = *reinterpret_cast<const float4*>(&Bm[(size_t)(col0 + lm) * HD + k0 + lk4]);
        As[lm][lk4 + 0] = av.x; As[lm][lk4 + 1] = av.y; As[lm][lk4 + 2] = av.z; As[lm][lk4 + 3] = av.w;
        Bs[lm][lk4 + 0] = bv.x; Bs[lm][lk4 + 1] = bv.y; Bs[lm][lk4 + 2] = bv.z; Bs[lm][lk4 + 3] = bv.w;
        __syncthreads();
        #pragma unroll
        for (int kk = 0; kk < 16; ++kk) {
            float a[4], bb[4];
            #pragma unroll
            for (int i = 0; i < 4; ++i) a[i] = As[ty * 4 + i][kk];
            #pragma unroll
            for (int j = 0; j < 4; ++j) bb[j] = Bs[tx * 4 + j][kk];
            #pragma unroll
            for (int i = 0; i < 4; ++i)
                #pragma unroll
                for (int j = 0; j < 4; ++j)
                    acc[i][j] += a[i] * bb[j];
        }
        __syncthreads();
    }

    int mv[4];
    #pragma unroll
    for (int j = 0; j < 4; ++j) mv[j] = mask[b * LK + col0 + tx * 4 + j];

    #pragma unroll
    for (int i = 0; i < 4; ++i) {
        int r = row0 + ty * 4 + i;
        #pragma unroll
        for (int j = 0; j < 4; ++j) {
            float s = tanhf(acc[i][j] * 0.125f) * 10.0f;
            if (mv[j]) s = -10.0f;
            Sout[(size_t)r * LK + col0 + tx * 4 + j] = s;
        }
    }
}

// =====================================================================
// Log-softmax fixup: one block per (b,h,q) row; attn = s - logsumexp(s)
// =====================================================================
__global__ __launch_bounds__(256) void lse_fixup(float* __restrict__ attn)
{
    __shared__ float red[8];
    float* p = attn + (size_t)blockIdx.x * LK;
    int tid = threadIdx.x;

    float vals[8];
    float m = -1e30f;
    #pragma unroll
    for (int j = 0; j < 8; ++j) {
        vals[j] = p[tid + j * 256];
        m = fmaxf(m, vals[j]);
    }
    #pragma unroll
    for (int o = 16; o; o >>= 1) m = fmaxf(m, __shfl_xor_sync(0xffffffffu, m, o));
    if ((tid & 31) == 0) red[tid >> 5] = m;
    __syncthreads();
    float bm = red[0];
    #pragma unroll
    for (int w = 1; w < 8; ++w) bm = fmaxf(bm, red[w]);
    __syncthreads();

    float s = 0.0f;
    #pragma unroll
    for (int j = 0; j < 8; ++j) s += __expf(vals[j] - bm);
    #pragma unroll
    for (int o = 16; o; o >>= 1) s += __shfl_xor_sync(0xffffffffu, s, o);
    if ((tid & 31) == 0) red[tid >> 5] = s;
    __syncthreads();
    float ts = 0.0f;
    #pragma unroll
    for (int w = 0; w < 8; ++w) ts += red[w];

    float lse = bm + logf(ts);
    #pragma unroll
    for (int j = 0; j < 8; ++j) p[tid + j * 256] = vals[j] - lse;
}

// =====================================================================
extern "C" void kernel_launch(void* const* d_in, const int* in_sizes, int n_in,
                              void* d_out, int out_size)
{
    const float* Q    = (const float*)d_in[0];
    const float* K    = (const float*)d_in[1];
    const float* V    = (const float*)d_in[2];
    const int*   mask = (const int*)  d_in[3];
    const float* Wq   = (const float*)d_in[4];
    const float* bq   = (const float*)d_in[5];
    const float* Wk   = (const float*)d_in[6];
    const float* bk   = (const float*)d_in[7];
    const float* Wv   = (const float*)d_in[8];
    const float* bv   = (const float*)d_in[9];
    const float* Wo   = (const float*)d_in[10];
    const float* bo   = (const float*)d_in[11];

    float* out  = (float*)d_out;
    float* attn = out + (size_t)B_ * LQ * DM;   // attn region follows `out`

    float *gq, *gk, *gv, *gho;
    cudaGetSymbolAddress((void**)&gq,  g_q);
    cudaGetSymbolAddress((void**)&gk,  g_k);
    cudaGetSymbolAddress((void**)&gv,  g_v);
    cudaGetSymbolAddress((void**)&gho, g_ho);

    dim3 blk(256);

    // 1) projections: [8192,512] @ [512,128] + bias
    dim3 gproj(HD / 64, (B_ * LQ) / 64, 1);
    gemm_nn<<<gproj, blk>>>(Q, DM, 0, 0, Wq, HD, 0, 0, bq, gq, HD, 0, 0, DM);
    gemm_nn<<<gproj, blk>>>(K, DM, 0, 0, Wk, HD, 0, 0, bk, gk, HD, 0, 0, DM);
    gemm_nn<<<gproj, blk>>>(V, DM, 0, 0, Wv, HD, 0, 0, bv, gv, HD, 0, 0, DM);

    // 2) scores (writes raw clipped/masked s into attn region)
    gemm_nt_scores<<<dim3(LK / 64, LQ / 64, B_ * NH), blk>>>(gq, gk, mask, attn);

    // 3) log-softmax fixup in place
    lse_fixup<<<B_ * NH * LQ, 256>>>(attn);

    // 4) head_out = attn @ v   (batched over 8 (b,h); N = 64)
    gemm_nn<<<dim3(1, LQ / 64, B_ * NH), blk>>>(
        attn, LK, 2L * LQ * LK, (long)LQ * LK,
        gv,   HD, (long)LK * HD, (long)DH,
        (const float*)0,
        gho,  HD, (long)LQ * HD, (long)DH,
        LK);

    // 5) out = head_out @ Wo + bo : [8192,128] @ [128,512]
    gemm_nn<<<dim3(DM / 64, (B_ * LQ) / 64, 1), blk>>>(
        gho, HD, 0, 0, Wo, DM, 0, 0, bo, out, DM, 0, 0, HD);
}